// round 1
// baseline (speedup 1.0000x reference)
#include <cuda_runtime.h>
#include <math.h>

#define NN      50000
#define EE      400000
#define IN_DIM  256
#define HID     128
#define TN      4
#define TE      6
#define NHEAD   4
#define DH      32
#define NT_MAX  792          // ceil(50000/64) + TN padding slack
#define INV_SQRT_D 0.17677669529663687f

// ---------------- device scratch (allocation-free contract) ----------------
__device__ __align__(16) float    g_h[NN * HID];
__device__ __align__(16) float    g_k[NN * HID];
__device__ __align__(16) float    g_q[NN * HID];
__device__ __align__(16) float    g_v[NN * HID];
__device__ __align__(16) float    g_agg[NN * HID];
__device__ __align__(16) float    g_a[EE * NHEAD];      // scores, then exp(scores-max)
__device__ __align__(16) unsigned g_amax[NN * NHEAD];   // order-preserving uint keys
__device__ __align__(16) float    g_den[NN * NHEAD];    // softmax denom, then reciprocal
__device__ int g_sorted[NT_MAX * 64];
__device__ int g_tiletype[NT_MAX];
__device__ int g_cnt[TN];
__device__ int g_cursor[TN];
__device__ int g_poff[TN + 1];

// order-preserving float<->uint for atomicMax over signed floats
__device__ __forceinline__ unsigned enc_f(float f) {
    unsigned u = __float_as_uint(f);
    return (u & 0x80000000u) ? ~u : (u | 0x80000000u);
}
__device__ __forceinline__ float dec_f(unsigned k) {
    unsigned u = (k & 0x80000000u) ? (k & 0x7fffffffu) : ~k;
    return __uint_as_float(u);
}

// ---------------- node counting sort by type (padded 64-node tiles) --------
__global__ void k_sort_init() {
    int i = blockIdx.x * blockDim.x + threadIdx.x;
    if (i < NT_MAX * 64) g_sorted[i] = -1;
    if (i < TN) { g_cnt[i] = 0; g_cursor[i] = 0; }
}

__global__ void k_hist(const int* __restrict__ ntype) {
    int i = blockIdx.x * blockDim.x + threadIdx.x;
    if (i < NN) atomicAdd(&g_cnt[ntype[i]], 1);
}

__global__ void k_scan() {
    int p = 0;
    for (int t = 0; t < TN; t++) {
        g_poff[t] = p;
        p = (p + g_cnt[t] + 63) & ~63;
    }
    g_poff[TN] = p;
    for (int j = 0; j < NT_MAX; j++) {
        int s = j * 64, ty = -1;
        for (int t = 0; t < TN; t++)
            if (s >= g_poff[t] && s < g_poff[t + 1]) ty = t;
        if (s >= p) ty = -1;
        g_tiletype[j] = ty;
    }
}

__global__ void k_scatter(const int* __restrict__ ntype) {
    int i = blockIdx.x * blockDim.x + threadIdx.x;
    if (i < NN) {
        int t = ntype[i];
        int pos = g_poff[t] + atomicAdd(&g_cursor[t], 1);
        g_sorted[pos] = i;
    }
}

// ---------------- typed linear: adapt (256->128) + bias + exact GELU -------
__global__ void k_adapt(const float* __restrict__ x, const float* __restrict__ W,
                        const float* __restrict__ b) {
    __shared__ float sW[32 * HID];
    int t = g_tiletype[blockIdx.x];
    if (t < 0) return;
    int tid = threadIdx.x, lane = tid & 31, wid = tid >> 5;
    int base = blockIdx.x * 64 + wid * 8;
    int idx[8];
#pragma unroll
    for (int n = 0; n < 8; n++) idx[n] = g_sorted[base + n];
    float acc[8][4];
#pragma unroll
    for (int n = 0; n < 8; n++)
#pragma unroll
        for (int r = 0; r < 4; r++) acc[n][r] = 0.f;
    const float* Wt = W + (size_t)t * IN_DIM * HID;

    for (int kc = 0; kc < IN_DIM / 32; kc++) {
        __syncthreads();
        for (int u = tid; u < 32 * HID; u += 256) sW[u] = Wt[kc * 32 * HID + u];
        __syncthreads();
        float hreg[8];
#pragma unroll
        for (int n = 0; n < 8; n++)
            hreg[n] = (idx[n] >= 0) ? x[idx[n] * IN_DIM + kc * 32 + lane] : 0.f;
#pragma unroll
        for (int kk = 0; kk < 32; kk++) {
            float w0 = sW[kk * HID + lane];
            float w1 = sW[kk * HID + lane + 32];
            float w2 = sW[kk * HID + lane + 64];
            float w3 = sW[kk * HID + lane + 96];
#pragma unroll
            for (int n = 0; n < 8; n++) {
                float hv = __shfl_sync(0xffffffffu, hreg[n], kk);
                acc[n][0] += hv * w0; acc[n][1] += hv * w1;
                acc[n][2] += hv * w2; acc[n][3] += hv * w3;
            }
        }
    }
    const float* bt = b + t * HID;
#pragma unroll
    for (int n = 0; n < 8; n++) {
        if (idx[n] < 0) continue;
#pragma unroll
        for (int r = 0; r < 4; r++) {
            float v0 = acc[n][r] + bt[lane + 32 * r];
            g_h[idx[n] * HID + lane + 32 * r] =
                0.5f * v0 * (1.f + erff(v0 * 0.7071067811865475f));
        }
    }
}

// ---------------- typed linear: k, q, v (128->128 x3) ----------------------
__global__ void k_kqv(const float* __restrict__ Wk, const float* __restrict__ Wq,
                      const float* __restrict__ Wv) {
    __shared__ float sW[32 * HID];
    int t = g_tiletype[blockIdx.x];
    if (t < 0) return;
    int tid = threadIdx.x, lane = tid & 31, wid = tid >> 5;
    int base = blockIdx.x * 64 + wid * 8;
    int idx[8];
#pragma unroll
    for (int n = 0; n < 8; n++) idx[n] = g_sorted[base + n];
    float hfull[8][4];
#pragma unroll
    for (int n = 0; n < 8; n++)
#pragma unroll
        for (int c = 0; c < 4; c++)
            hfull[n][c] = (idx[n] >= 0) ? g_h[idx[n] * HID + c * 32 + lane] : 0.f;

#pragma unroll 1
    for (int m = 0; m < 3; m++) {
        const float* Wt = ((m == 0) ? Wk : (m == 1) ? Wq : Wv) + (size_t)t * HID * HID;
        float* go = (m == 0) ? g_k : (m == 1) ? g_q : g_v;
        float acc[8][4];
#pragma unroll
        for (int n = 0; n < 8; n++)
#pragma unroll
            for (int r = 0; r < 4; r++) acc[n][r] = 0.f;

        for (int kc = 0; kc < 4; kc++) {
            __syncthreads();
            for (int u = tid; u < 32 * HID; u += 256) sW[u] = Wt[kc * 32 * HID + u];
            __syncthreads();
#pragma unroll
            for (int kk = 0; kk < 32; kk++) {
                float w0 = sW[kk * HID + lane];
                float w1 = sW[kk * HID + lane + 32];
                float w2 = sW[kk * HID + lane + 64];
                float w3 = sW[kk * HID + lane + 96];
#pragma unroll
                for (int n = 0; n < 8; n++) {
                    float hv = __shfl_sync(0xffffffffu, hfull[n][kc], kk);
                    acc[n][0] += hv * w0; acc[n][1] += hv * w1;
                    acc[n][2] += hv * w2; acc[n][3] += hv * w3;
                }
            }
        }
#pragma unroll
        for (int n = 0; n < 8; n++) {
            if (idx[n] < 0) continue;
#pragma unroll
            for (int r = 0; r < 4; r++) go[idx[n] * HID + lane + 32 * r] = acc[n][r];
        }
    }
}

// ---------------- typed linear: Wla + skip blend + layernorm ---------------
__global__ void k_post(const float* __restrict__ Wla, const float* __restrict__ skipv,
                       const float* __restrict__ gam, const float* __restrict__ bet) {
    __shared__ float sW[32 * HID];
    int t = g_tiletype[blockIdx.x];
    if (t < 0) return;
    int tid = threadIdx.x, lane = tid & 31, wid = tid >> 5;
    int base = blockIdx.x * 64 + wid * 8;
    int idx[8];
#pragma unroll
    for (int n = 0; n < 8; n++) idx[n] = g_sorted[base + n];
    float hfull[8][4];
#pragma unroll
    for (int n = 0; n < 8; n++)
#pragma unroll
        for (int c = 0; c < 4; c++)
            hfull[n][c] = (idx[n] >= 0) ? g_agg[idx[n] * HID + c * 32 + lane] : 0.f;

    const float* Wt = Wla + (size_t)t * HID * HID;
    float acc[8][4];
#pragma unroll
    for (int n = 0; n < 8; n++)
#pragma unroll
        for (int r = 0; r < 4; r++) acc[n][r] = 0.f;

    for (int kc = 0; kc < 4; kc++) {
        __syncthreads();
        for (int u = tid; u < 32 * HID; u += 256) sW[u] = Wt[kc * 32 * HID + u];
        __syncthreads();
#pragma unroll
        for (int kk = 0; kk < 32; kk++) {
            float w0 = sW[kk * HID + lane];
            float w1 = sW[kk * HID + lane + 32];
            float w2 = sW[kk * HID + lane + 64];
            float w3 = sW[kk * HID + lane + 96];
#pragma unroll
            for (int n = 0; n < 8; n++) {
                float hv = __shfl_sync(0xffffffffu, hfull[n][kc], kk);
                acc[n][0] += hv * w0; acc[n][1] += hv * w1;
                acc[n][2] += hv * w2; acc[n][3] += hv * w3;
            }
        }
    }
    float alpha = 1.f / (1.f + expf(-skipv[t]));
#pragma unroll
    for (int n = 0; n < 8; n++) {
        if (idx[n] < 0) continue;   // warp-uniform branch (idx same across lanes)
        float v[4];
#pragma unroll
        for (int r = 0; r < 4; r++) {
            float hold = g_h[idx[n] * HID + lane + 32 * r];
            v[r] = acc[n][r] * alpha + hold * (1.f - alpha);
        }
        float s1 = v[0] + v[1] + v[2] + v[3];
        float s2 = v[0]*v[0] + v[1]*v[1] + v[2]*v[2] + v[3]*v[3];
#pragma unroll
        for (int o = 16; o > 0; o >>= 1) {
            s1 += __shfl_xor_sync(0xffffffffu, s1, o);
            s2 += __shfl_xor_sync(0xffffffffu, s2, o);
        }
        float mu = s1 * (1.f / 128.f);
        float var = s2 * (1.f / 128.f) - mu * mu;
        float rstd = rsqrtf(var + 1e-5f);
#pragma unroll
        for (int r = 0; r < 4; r++) {
            int j = lane + 32 * r;
            g_h[idx[n] * HID + j] = (v[r] - mu) * rstd * gam[j] + bet[j];
        }
    }
}

// ---------------- per-layer zero init ---------------------------------------
__global__ void k_zero() {
    int i = blockIdx.x * blockDim.x + threadIdx.x;
    if (i < NN * HID) g_agg[i] = 0.f;
    if (i < NN * NHEAD) { g_den[i] = 0.f; g_amax[i] = 0u; }
}

// ---------------- edge scores + segment max (fused) -------------------------
__global__ void k_score(const float* __restrict__ Wa_l, const float* __restrict__ pri_l,
                        const int* __restrict__ src, const int* __restrict__ dst,
                        const int* __restrict__ et) {
    __shared__ float sWa[TE * DH * DH];
    __shared__ float spri[TE];
    int h = blockIdx.y;
    int tid = threadIdx.x, lane = tid & 31, wid = tid >> 5;
    for (int u = tid; u < TE * DH * DH; u += blockDim.x) sWa[u] = Wa_l[h * TE * DH * DH + u];
    if (tid < TE) spri[tid] = pri_l[h * TE + tid];
    __syncthreads();
    int nwarp = (gridDim.x * blockDim.x) >> 5;
    for (int e = blockIdx.x * (blockDim.x >> 5) + wid; e < EE; e += nwarp) {
        int s = src[e], dd = dst[e], t = et[e];
        float kv = g_k[s * HID + h * DH + lane];
        float qv = g_q[dd * HID + h * DH + lane];
        const float* w = &sWa[t * DH * DH];
        float kw = 0.f;
#pragma unroll
        for (int d = 0; d < 32; d++)
            kw += __shfl_sync(0xffffffffu, kv, d) * w[d * 32 + lane];
        float p = kw * qv;
#pragma unroll
        for (int o = 16; o > 0; o >>= 1) p += __shfl_xor_sync(0xffffffffu, p, o);
        if (lane == 0) {
            float sc = p * spri[t] * INV_SQRT_D;
            g_a[e * NHEAD + h] = sc;
            atomicMax(&g_amax[dd * NHEAD + h], enc_f(sc));
        }
    }
}

// ---------------- exp(score - max) + segment sum -----------------------------
__global__ void k_exp(const int* __restrict__ dst) {
    int i = blockIdx.x * blockDim.x + threadIdx.x;
    if (i >= EE * NHEAD) return;
    int e = i >> 2, h = i & 3;
    int dd = dst[e];
    float ex = expf(g_a[i] - dec_f(g_amax[dd * NHEAD + h]));
    g_a[i] = ex;
    atomicAdd(&g_den[dd * NHEAD + h], ex);
}

__global__ void k_inv() {
    int i = blockIdx.x * blockDim.x + threadIdx.x;
    if (i >= NN * NHEAD) return;
    float d = g_den[i];
    g_den[i] = (d > 0.f) ? 1.f / d : 0.f;
}

// ---------------- message transform + weighted aggregation -------------------
__global__ void k_agg(const float* __restrict__ Wm_l, const int* __restrict__ src,
                      const int* __restrict__ dst, const int* __restrict__ et) {
    __shared__ float sWm[TE * DH * DH];
    int h = blockIdx.y;
    int tid = threadIdx.x, lane = tid & 31, wid = tid >> 5;
    for (int u = tid; u < TE * DH * DH; u += blockDim.x) sWm[u] = Wm_l[h * TE * DH * DH + u];
    __syncthreads();
    int nwarp = (gridDim.x * blockDim.x) >> 5;
    for (int e = blockIdx.x * (blockDim.x >> 5) + wid; e < EE; e += nwarp) {
        int s = src[e], dd = dst[e], t = et[e];
        float vv = g_v[s * HID + h * DH + lane];
        const float* w = &sWm[t * DH * DH];
        float mo = 0.f;
#pragma unroll
        for (int d = 0; d < 32; d++)
            mo += __shfl_sync(0xffffffffu, vv, d) * w[d * 32 + lane];
        float attn = g_a[e * NHEAD + h] * g_den[dd * NHEAD + h];
        atomicAdd(&g_agg[dd * HID + h * DH + lane], attn * mo);
    }
}

// ---------------- output projection ------------------------------------------
__global__ void k_out(const float* __restrict__ Wo, const float* __restrict__ bo,
                      float* __restrict__ out) {
    __shared__ float sW[HID * 16];
    int tid = threadIdx.x;
    for (int u = tid; u < HID * 16; u += blockDim.x) sW[u] = Wo[u];
    __syncthreads();
    int gt = blockIdx.x * blockDim.x + tid;
    int stride = gridDim.x * blockDim.x;
    for (int i = gt; i < NN * 16; i += stride) {
        int nidx = i >> 4, j = i & 15;
        const float4* hr = reinterpret_cast<const float4*>(&g_h[nidx * HID]);
        float acc = bo[j];
#pragma unroll
        for (int kq = 0; kq < HID / 4; kq++) {
            float4 hv = hr[kq];
            acc += hv.x * sW[(4 * kq + 0) * 16 + j];
            acc += hv.y * sW[(4 * kq + 1) * 16 + j];
            acc += hv.z * sW[(4 * kq + 2) * 16 + j];
            acc += hv.w * sW[(4 * kq + 3) * 16 + j];
        }
        out[i] = acc;
    }
}

// ---------------- launch ------------------------------------------------------
extern "C" void kernel_launch(void* const* d_in, const int* in_sizes, int n_in,
                              void* d_out, int out_size) {
    const float* x       = (const float*)d_in[0];
    const float* adapt_W = (const float*)d_in[1];
    const float* adapt_b = (const float*)d_in[2];
    const float* Wk      = (const float*)d_in[3];
    const float* Wq      = (const float*)d_in[4];
    const float* Wv      = (const float*)d_in[5];
    const float* pri     = (const float*)d_in[6];
    const float* Wa      = (const float*)d_in[7];
    const float* Wm      = (const float*)d_in[8];
    const float* Wla     = (const float*)d_in[9];
    const float* skip    = (const float*)d_in[10];
    const float* gamma   = (const float*)d_in[11];
    const float* beta    = (const float*)d_in[12];
    const float* out_W   = (const float*)d_in[13];
    const float* out_b   = (const float*)d_in[14];
    const int*   ntype   = (const int*)d_in[15];
    const int*   etype   = (const int*)d_in[16];
    const int*   src     = (const int*)d_in[17];
    const int*   dst     = (const int*)d_in[18];
    float* out = (float*)d_out;

    // node counting sort by type (padded 64-node tiles)
    k_sort_init<<<(NT_MAX * 64 + 255) / 256, 256>>>();
    k_hist<<<(NN + 255) / 256, 256>>>(ntype);
    k_scan<<<1, 1>>>();
    k_scatter<<<(NN + 255) / 256, 256>>>(ntype);

    // adapt linear + GELU
    k_adapt<<<NT_MAX, 256>>>(x, adapt_W, adapt_b);

    for (int l = 0; l < 2; l++) {
        k_zero<<<(NN * HID + 255) / 256, 256>>>();
        k_kqv<<<NT_MAX, 256>>>(Wk + (size_t)l * TN * HID * HID,
                               Wq + (size_t)l * TN * HID * HID,
                               Wv + (size_t)l * TN * HID * HID);
        dim3 eg(296, NHEAD);
        k_score<<<eg, 256>>>(Wa + (size_t)l * NHEAD * TE * DH * DH,
                             pri + (size_t)l * NHEAD * TE, src, dst, etype);
        k_exp<<<(EE * NHEAD + 255) / 256, 256>>>(dst);
        k_inv<<<(NN * NHEAD + 255) / 256, 256>>>();
        k_agg<<<eg, 256>>>(Wm + (size_t)l * NHEAD * TE * DH * DH, src, dst, etype);
        k_post<<<NT_MAX, 256>>>(Wla + (size_t)l * TN * HID * HID,
                                skip + (size_t)l * TN,
                                gamma + (size_t)l * HID,
                                beta + (size_t)l * HID);
    }
    k_out<<<400, 256>>>(out_W, out_b, out);
}

// round 2
// speedup vs baseline: 1.7804x; 1.7804x over previous
#include <cuda_runtime.h>
#include <math.h>

#define NN      50000
#define EE      400000
#define IN_DIM  256
#define HID     128
#define TN      4
#define TE      6
#define NHEAD   4
#define DH      32
#define NT_MAX  792
#define INV_SQRT_D 0.17677669529663687f

// ---------------- device scratch (allocation-free contract) ----------------
__device__ __align__(16) float g_h[NN * HID];
__device__ __align__(16) float g_k[NN * HID];
__device__ __align__(16) float g_q[NN * HID];
__device__ __align__(16) float g_v[NN * HID];
__device__ __align__(16) float g_agg[NN * HID];
__device__ __align__(16) float g_khat[(size_t)NN * TE * NHEAD * DH];  // 153.6 MB
__device__ __align__(16) float g_vhat[(size_t)NN * TE * NHEAD * DH];  // 153.6 MB

// node-type sort
__device__ int g_sorted[NT_MAX * 64];
__device__ int g_tiletype[NT_MAX];
__device__ int g_cnt[TN];
__device__ int g_cursor[TN];
__device__ int g_poff[TN + 1];

// dst-CSR for edges
__device__ int g_deg[NN];
__device__ int g_cur[NN];
__device__ int g_rows[NN + 1];
__device__ int g_epack[EE];   // src | (etype << 16)

// ---------------- node counting sort by type (padded 64-node tiles) --------
__global__ void k_sort_init() {
    int i = blockIdx.x * blockDim.x + threadIdx.x;
    if (i < NT_MAX * 64) g_sorted[i] = -1;
    if (i < TN) { g_cnt[i] = 0; g_cursor[i] = 0; }
    if (i < NN) { g_deg[i] = 0; g_cur[i] = 0; }
}

__global__ void k_hist(const int* __restrict__ ntype) {
    int i = blockIdx.x * blockDim.x + threadIdx.x;
    if (i < NN) atomicAdd(&g_cnt[ntype[i]], 1);
}

__global__ void k_scan() {
    int p = 0;
    for (int t = 0; t < TN; t++) {
        g_poff[t] = p;
        p = (p + g_cnt[t] + 63) & ~63;
    }
    g_poff[TN] = p;
    for (int j = 0; j < NT_MAX; j++) {
        int s = j * 64, ty = -1;
        for (int t = 0; t < TN; t++)
            if (s >= g_poff[t] && s < g_poff[t + 1]) ty = t;
        if (s >= p) ty = -1;
        g_tiletype[j] = ty;
    }
}

__global__ void k_scatter(const int* __restrict__ ntype) {
    int i = blockIdx.x * blockDim.x + threadIdx.x;
    if (i < NN) {
        int t = ntype[i];
        int pos = g_poff[t] + atomicAdd(&g_cursor[t], 1);
        g_sorted[pos] = i;
    }
}

// ---------------- edge CSR build (once; edges layer-invariant) -------------
__global__ void k_edeg(const int* __restrict__ dst) {
    int i = blockIdx.x * blockDim.x + threadIdx.x;
    if (i < EE) atomicAdd(&g_deg[dst[i]], 1);
}

__global__ void k_escan() {   // single block, 1024 threads
    __shared__ int sp[1024];
    const int C = (NN + 1023) / 1024;   // 49
    int tid = threadIdx.x;
    int s = 0;
    for (int j = 0; j < C; j++) {
        int idx = tid * C + j;
        if (idx < NN) s += g_deg[idx];
    }
    sp[tid] = s;
    __syncthreads();
    for (int o = 1; o < 1024; o <<= 1) {
        int t = (tid >= o) ? sp[tid - o] : 0;
        __syncthreads();
        sp[tid] += t;
        __syncthreads();
    }
    int run = sp[tid] - s;   // exclusive prefix of this thread's chunk
    for (int j = 0; j < C; j++) {
        int idx = tid * C + j;
        if (idx < NN) { g_rows[idx] = run; run += g_deg[idx]; }
    }
    if (tid == 1023) g_rows[NN] = sp[1023];
}

__global__ void k_escatter(const int* __restrict__ src, const int* __restrict__ dst,
                           const int* __restrict__ et) {
    int i = blockIdx.x * blockDim.x + threadIdx.x;
    if (i < EE) {
        int d = dst[i];
        int pos = g_rows[d] + atomicAdd(&g_cur[d], 1);
        g_epack[pos] = src[i] | (et[i] << 16);
    }
}

// ---------------- typed linear: adapt (256->128) + bias + exact GELU -------
__global__ void k_adapt(const float* __restrict__ x, const float* __restrict__ W,
                        const float* __restrict__ b) {
    __shared__ float sW[32 * HID];
    int t = g_tiletype[blockIdx.x];
    if (t < 0) return;
    int tid = threadIdx.x, lane = tid & 31, wid = tid >> 5;
    int base = blockIdx.x * 64 + wid * 8;
    int idx[8];
#pragma unroll
    for (int n = 0; n < 8; n++) idx[n] = g_sorted[base + n];
    float acc[8][4];
#pragma unroll
    for (int n = 0; n < 8; n++)
#pragma unroll
        for (int r = 0; r < 4; r++) acc[n][r] = 0.f;
    const float* Wt = W + (size_t)t * IN_DIM * HID;

    for (int kc = 0; kc < IN_DIM / 32; kc++) {
        __syncthreads();
        for (int u = tid; u < 32 * HID; u += 256) sW[u] = Wt[kc * 32 * HID + u];
        __syncthreads();
        float hreg[8];
#pragma unroll
        for (int n = 0; n < 8; n++)
            hreg[n] = (idx[n] >= 0) ? x[idx[n] * IN_DIM + kc * 32 + lane] : 0.f;
#pragma unroll
        for (int kk = 0; kk < 32; kk++) {
            float w0 = sW[kk * HID + lane];
            float w1 = sW[kk * HID + lane + 32];
            float w2 = sW[kk * HID + lane + 64];
            float w3 = sW[kk * HID + lane + 96];
#pragma unroll
            for (int n = 0; n < 8; n++) {
                float hv = __shfl_sync(0xffffffffu, hreg[n], kk);
                acc[n][0] += hv * w0; acc[n][1] += hv * w1;
                acc[n][2] += hv * w2; acc[n][3] += hv * w3;
            }
        }
    }
    const float* bt = b + t * HID;
#pragma unroll
    for (int n = 0; n < 8; n++) {
        if (idx[n] < 0) continue;
#pragma unroll
        for (int r = 0; r < 4; r++) {
            float v0 = acc[n][r] + bt[lane + 32 * r];
            g_h[idx[n] * HID + lane + 32 * r] =
                0.5f * v0 * (1.f + erff(v0 * 0.7071067811865475f));
        }
    }
}

// ---------------- typed linear: k, q, v (128->128 x3) ----------------------
__global__ void k_kqv(const float* __restrict__ Wk, const float* __restrict__ Wq,
                      const float* __restrict__ Wv) {
    __shared__ float sW[32 * HID];
    int t = g_tiletype[blockIdx.x];
    if (t < 0) return;
    int tid = threadIdx.x, lane = tid & 31, wid = tid >> 5;
    int base = blockIdx.x * 64 + wid * 8;
    int idx[8];
#pragma unroll
    for (int n = 0; n < 8; n++) idx[n] = g_sorted[base + n];
    float hfull[8][4];
#pragma unroll
    for (int n = 0; n < 8; n++)
#pragma unroll
        for (int c = 0; c < 4; c++)
            hfull[n][c] = (idx[n] >= 0) ? g_h[idx[n] * HID + c * 32 + lane] : 0.f;

#pragma unroll 1
    for (int m = 0; m < 3; m++) {
        const float* Wt = ((m == 0) ? Wk : (m == 1) ? Wq : Wv) + (size_t)t * HID * HID;
        float* go = (m == 0) ? g_k : (m == 1) ? g_q : g_v;
        float acc[8][4];
#pragma unroll
        for (int n = 0; n < 8; n++)
#pragma unroll
            for (int r = 0; r < 4; r++) acc[n][r] = 0.f;

        for (int kc = 0; kc < 4; kc++) {
            __syncthreads();
            for (int u = tid; u < 32 * HID; u += 256) sW[u] = Wt[kc * 32 * HID + u];
            __syncthreads();
#pragma unroll
            for (int kk = 0; kk < 32; kk++) {
                float w0 = sW[kk * HID + lane];
                float w1 = sW[kk * HID + lane + 32];
                float w2 = sW[kk * HID + lane + 64];
                float w3 = sW[kk * HID + lane + 96];
#pragma unroll
                for (int n = 0; n < 8; n++) {
                    float hv = __shfl_sync(0xffffffffu, hfull[n][kc], kk);
                    acc[n][0] += hv * w0; acc[n][1] += hv * w1;
                    acc[n][2] += hv * w2; acc[n][3] += hv * w3;
                }
            }
        }
#pragma unroll
        for (int n = 0; n < 8; n++) {
            if (idx[n] < 0) continue;
#pragma unroll
            for (int r = 0; r < 4; r++) go[idx[n] * HID + lane + 32 * r] = acc[n][r];
        }
    }
}

// ---------------- khat/vhat precompute: k·Wa·pri/√D and v·Wm ---------------
// grid (ceil(NN/32), NHEAD), block 256; warp handles 4 consecutive nodes.
__global__ void k_khv(const float* __restrict__ Wa_l, const float* __restrict__ Wm_l,
                      const float* __restrict__ pri_l) {
    __shared__ float sA[TE * DH * DH];
    __shared__ float sM[TE * DH * DH];
    int h = blockIdx.y;
    int tid = threadIdx.x, lane = tid & 31, wid = tid >> 5;
    for (int u = tid; u < TE * DH * DH; u += 256) {
        int t = u >> 10;
        sA[u] = Wa_l[h * TE * DH * DH + u] * (pri_l[h * TE + t] * INV_SQRT_D);
        sM[u] = Wm_l[h * TE * DH * DH + u];
    }
    __syncthreads();

    int nb = blockIdx.x * 32 + wid * 4;
    float kv[4], vv[4];
#pragma unroll
    for (int n = 0; n < 4; n++) {
        int idx = nb + n;
        kv[n] = (idx < NN) ? g_k[idx * HID + h * DH + lane] : 0.f;
        vv[n] = (idx < NN) ? g_v[idx * HID + h * DH + lane] : 0.f;
    }
    float ak[4][TE], av[4][TE];
#pragma unroll
    for (int n = 0; n < 4; n++)
#pragma unroll
        for (int t = 0; t < TE; t++) { ak[n][t] = 0.f; av[n][t] = 0.f; }

#pragma unroll 4
    for (int d = 0; d < DH; d++) {
        float hk[4], hv[4];
#pragma unroll
        for (int n = 0; n < 4; n++) {
            hk[n] = __shfl_sync(0xffffffffu, kv[n], d);
            hv[n] = __shfl_sync(0xffffffffu, vv[n], d);
        }
#pragma unroll
        for (int t = 0; t < TE; t++) {
            float wa = sA[t * 1024 + d * 32 + lane];
            float wm = sM[t * 1024 + d * 32 + lane];
#pragma unroll
            for (int n = 0; n < 4; n++) {
                ak[n][t] += hk[n] * wa;
                av[n][t] += hv[n] * wm;
            }
        }
    }
#pragma unroll
    for (int n = 0; n < 4; n++) {
        int idx = nb + n;
        if (idx >= NN) continue;
        size_t base = (((size_t)idx * TE) * NHEAD + h) * DH + lane;
#pragma unroll
        for (int t = 0; t < TE; t++) {
            g_khat[base + (size_t)t * NHEAD * DH] = ak[n][t];
            g_vhat[base + (size_t)t * NHEAD * DH] = av[n][t];
        }
    }
}

// ---------------- fused edge softmax + aggregation (CSR, atomic-free) ------
// warp = (dst, head); online softmax over incoming edges in registers.
__global__ void k_edge() {
    int wid = threadIdx.x >> 5, lane = threadIdx.x & 31;
    int gw = blockIdx.x * 8 + wid;
    int dstn = gw >> 2, h = gw & 3;
    if (dstn >= NN) return;
    int rs = g_rows[dstn], re = g_rows[dstn + 1];
    float qv = g_q[dstn * HID + h * DH + lane];
    float M = -INFINITY, S = 0.f, acc = 0.f;
    for (int p = rs; p < re; p++) {
        int pk = g_epack[p];
        int s = pk & 0xffff, t = pk >> 16;
        size_t base = (((size_t)s * TE + t) * NHEAD + h) * DH;
        float ph = g_khat[base + lane] * qv;
#pragma unroll
        for (int o = 16; o > 0; o >>= 1)
            ph += __shfl_xor_sync(0xffffffffu, ph, o);
        float nm = fmaxf(M, ph);
        float scale = __expf(M - nm);     // 0 on first edge (M = -inf)
        float w = __expf(ph - nm);
        S = S * scale + w;
        acc = acc * scale + w * g_vhat[base + lane];
        M = nm;
    }
    g_agg[dstn * HID + h * DH + lane] = (S > 0.f) ? acc / S : 0.f;
}

// ---------------- typed linear: Wla + skip blend + layernorm ---------------
__global__ void k_post(const float* __restrict__ Wla, const float* __restrict__ skipv,
                       const float* __restrict__ gam, const float* __restrict__ bet) {
    __shared__ float sW[32 * HID];
    int t = g_tiletype[blockIdx.x];
    if (t < 0) return;
    int tid = threadIdx.x, lane = tid & 31, wid = tid >> 5;
    int base = blockIdx.x * 64 + wid * 8;
    int idx[8];
#pragma unroll
    for (int n = 0; n < 8; n++) idx[n] = g_sorted[base + n];
    float hfull[8][4];
#pragma unroll
    for (int n = 0; n < 8; n++)
#pragma unroll
        for (int c = 0; c < 4; c++)
            hfull[n][c] = (idx[n] >= 0) ? g_agg[idx[n] * HID + c * 32 + lane] : 0.f;

    const float* Wt = Wla + (size_t)t * HID * HID;
    float acc[8][4];
#pragma unroll
    for (int n = 0; n < 8; n++)
#pragma unroll
        for (int r = 0; r < 4; r++) acc[n][r] = 0.f;

    for (int kc = 0; kc < 4; kc++) {
        __syncthreads();
        for (int u = tid; u < 32 * HID; u += 256) sW[u] = Wt[kc * 32 * HID + u];
        __syncthreads();
#pragma unroll
        for (int kk = 0; kk < 32; kk++) {
            float w0 = sW[kk * HID + lane];
            float w1 = sW[kk * HID + lane + 32];
            float w2 = sW[kk * HID + lane + 64];
            float w3 = sW[kk * HID + lane + 96];
#pragma unroll
            for (int n = 0; n < 8; n++) {
                float hv = __shfl_sync(0xffffffffu, hfull[n][kc], kk);
                acc[n][0] += hv * w0; acc[n][1] += hv * w1;
                acc[n][2] += hv * w2; acc[n][3] += hv * w3;
            }
        }
    }
    float alpha = 1.f / (1.f + expf(-skipv[t]));
#pragma unroll
    for (int n = 0; n < 8; n++) {
        if (idx[n] < 0) continue;
        float v[4];
#pragma unroll
        for (int r = 0; r < 4; r++) {
            float hold = g_h[idx[n] * HID + lane + 32 * r];
            v[r] = acc[n][r] * alpha + hold * (1.f - alpha);
        }
        float s1 = v[0] + v[1] + v[2] + v[3];
        float s2 = v[0]*v[0] + v[1]*v[1] + v[2]*v[2] + v[3]*v[3];
#pragma unroll
        for (int o = 16; o > 0; o >>= 1) {
            s1 += __shfl_xor_sync(0xffffffffu, s1, o);
            s2 += __shfl_xor_sync(0xffffffffu, s2, o);
        }
        float mu = s1 * (1.f / 128.f);
        float var = s2 * (1.f / 128.f) - mu * mu;
        float rstd = rsqrtf(var + 1e-5f);
#pragma unroll
        for (int r = 0; r < 4; r++) {
            int j = lane + 32 * r;
            g_h[idx[n] * HID + j] = (v[r] - mu) * rstd * gam[j] + bet[j];
        }
    }
}

// ---------------- output projection ------------------------------------------
__global__ void k_out(const float* __restrict__ Wo, const float* __restrict__ bo,
                      float* __restrict__ out) {
    __shared__ float sW[HID * 16];
    int tid = threadIdx.x;
    for (int u = tid; u < HID * 16; u += blockDim.x) sW[u] = Wo[u];
    __syncthreads();
    int gt = blockIdx.x * blockDim.x + tid;
    int stride = gridDim.x * blockDim.x;
    for (int i = gt; i < NN * 16; i += stride) {
        int nidx = i >> 4, j = i & 15;
        const float4* hr = reinterpret_cast<const float4*>(&g_h[nidx * HID]);
        float acc = bo[j];
#pragma unroll
        for (int kq = 0; kq < HID / 4; kq++) {
            float4 hv = hr[kq];
            acc += hv.x * sW[(4 * kq + 0) * 16 + j];
            acc += hv.y * sW[(4 * kq + 1) * 16 + j];
            acc += hv.z * sW[(4 * kq + 2) * 16 + j];
            acc += hv.w * sW[(4 * kq + 3) * 16 + j];
        }
        out[i] = acc;
    }
}

// ---------------- launch ------------------------------------------------------
extern "C" void kernel_launch(void* const* d_in, const int* in_sizes, int n_in,
                              void* d_out, int out_size) {
    const float* x       = (const float*)d_in[0];
    const float* adapt_W = (const float*)d_in[1];
    const float* adapt_b = (const float*)d_in[2];
    const float* Wk      = (const float*)d_in[3];
    const float* Wq      = (const float*)d_in[4];
    const float* Wv      = (const float*)d_in[5];
    const float* pri     = (const float*)d_in[6];
    const float* Wa      = (const float*)d_in[7];
    const float* Wm      = (const float*)d_in[8];
    const float* Wla     = (const float*)d_in[9];
    const float* skip    = (const float*)d_in[10];
    const float* gamma   = (const float*)d_in[11];
    const float* beta    = (const float*)d_in[12];
    const float* out_W   = (const float*)d_in[13];
    const float* out_b   = (const float*)d_in[14];
    const int*   ntype   = (const int*)d_in[15];
    const int*   etype   = (const int*)d_in[16];
    const int*   src     = (const int*)d_in[17];
    const int*   dst     = (const int*)d_in[18];
    float* out = (float*)d_out;

    // node counting sort by type + per-run CSR state init
    k_sort_init<<<(NT_MAX * 64 + 255) / 256, 256>>>();
    k_hist<<<(NN + 255) / 256, 256>>>(ntype);
    k_scan<<<1, 1>>>();
    k_scatter<<<(NN + 255) / 256, 256>>>(ntype);

    // edge CSR by dst (built once; reused by both layers)
    k_edeg<<<(EE + 255) / 256, 256>>>(dst);
    k_escan<<<1, 1024>>>();
    k_escatter<<<(EE + 255) / 256, 256>>>(src, dst, etype);

    // adapt linear + GELU
    k_adapt<<<NT_MAX, 256>>>(x, adapt_W, adapt_b);

    for (int l = 0; l < 2; l++) {
        k_kqv<<<NT_MAX, 256>>>(Wk + (size_t)l * TN * HID * HID,
                               Wq + (size_t)l * TN * HID * HID,
                               Wv + (size_t)l * TN * HID * HID);
        dim3 hg((NN + 31) / 32, NHEAD);
        k_khv<<<hg, 256>>>(Wa + (size_t)l * NHEAD * TE * DH * DH,
                           Wm + (size_t)l * NHEAD * TE * DH * DH,
                           pri + (size_t)l * NHEAD * TE);
        k_edge<<<(NN * NHEAD + 7) / 8, 256>>>();
        k_post<<<NT_MAX, 256>>>(Wla + (size_t)l * TN * HID * HID,
                                skip + (size_t)l * TN,
                                gamma + (size_t)l * HID,
                                beta + (size_t)l * HID);
    }
    k_out<<<400, 256>>>(out_W, out_b, out);
}

// round 3
// speedup vs baseline: 1.9568x; 1.0991x over previous
#include <cuda_runtime.h>
#include <math.h>

#define NN      50000
#define EE      400000
#define IN_DIM  256
#define HID     128
#define TN      4
#define TE      6
#define NHEAD   4
#define DH      32
#define NT128   396                 // max 128-row tiles (50000 + 4*127 padded)
#define NN_P    (NT128 * 128)       // 50688 padded node positions
#define NT64    (NT128 * 2)
#define INV_SQRT_D 0.17677669529663687f

typedef unsigned long long u64;

// ---------------- f32x2 helpers (FFMA2 only reachable via PTX) -------------
__device__ __forceinline__ void ffma2(u64& d, u64 a, u64 b) {
    asm("fma.rn.f32x2 %0, %1, %2, %0;" : "+l"(d) : "l"(a), "l"(b));
}
__device__ __forceinline__ u64 dup2(float v) {
    u64 r; asm("mov.b64 %0, {%1, %1};" : "=l"(r) : "f"(v)); return r;
}
__device__ __forceinline__ void unpack2(u64 p, float& lo, float& hi) {
    asm("mov.b64 {%0, %1}, %2;" : "=f"(lo), "=f"(hi) : "l"(p));
}

// ---------------- device scratch (allocation-free contract) ----------------
// all node-indexed arrays live in PERMUTED (type-sorted, 128-padded) order
__device__ __align__(16) float g_h[NN_P * HID];
__device__ __align__(16) float g_k[NN_P * HID];       // also k_post scratch
__device__ __align__(16) float g_q[NN_P * HID];
__device__ __align__(16) float g_v[NN_P * HID];
__device__ __align__(16) float g_agg[NN_P * HID];
__device__ __align__(16) float g_khat[(size_t)NN_P * TE * NHEAD * DH];
__device__ __align__(16) float g_vhat[(size_t)NN_P * TE * NHEAD * DH];

__device__ int g_ord[NN_P];        // pos -> orig (-1 pad)
__device__ int g_pos[NN];          // orig -> pos
__device__ int g_tiletype128[NT128];
__device__ int g_cnt[TN];
__device__ int g_cursor[TN];
__device__ int g_poff[TN + 1];

__device__ int g_deg[NN_P];
__device__ int g_cur[NN_P];
__device__ int g_rows[NN_P + 1];
__device__ int g_epack[EE];        // src_pos | (etype << 16)

// ---------------- setup ------------------------------------------------------
__global__ void k_init() {
    int i = blockIdx.x * blockDim.x + threadIdx.x;
    if (i < NN_P) { g_ord[i] = -1; g_deg[i] = 0; g_cur[i] = 0; }
    if (i < TN) { g_cnt[i] = 0; g_cursor[i] = 0; }
}
__global__ void k_hist(const int* __restrict__ ntype) {
    int i = blockIdx.x * blockDim.x + threadIdx.x;
    if (i < NN) atomicAdd(&g_cnt[ntype[i]], 1);
}
__global__ void k_scan1() {
    int p = 0;
    for (int t = 0; t < TN; t++) { g_poff[t] = p; p += (g_cnt[t] + 127) & ~127; }
    g_poff[TN] = p;
    for (int j = 0; j < NT128; j++) {
        int s = j * 128, ty = -1;
        for (int t = 0; t < TN; t++)
            if (s >= g_poff[t] && s < g_poff[t + 1]) ty = t;
        g_tiletype128[j] = ty;
    }
}
__global__ void k_nscatter(const int* __restrict__ ntype) {
    int i = blockIdx.x * blockDim.x + threadIdx.x;
    if (i < NN) {
        int t = ntype[i];
        int pos = g_poff[t] + atomicAdd(&g_cursor[t], 1);
        g_ord[pos] = i;
        g_pos[i] = pos;
    }
}
__global__ void k_edeg(const int* __restrict__ dst) {
    int i = blockIdx.x * blockDim.x + threadIdx.x;
    if (i < EE) atomicAdd(&g_deg[g_pos[dst[i]]], 1);
}
__global__ void k_escan() {   // single block, 1024 threads
    __shared__ int sp[1024];
    const int C = (NN_P + 1023) / 1024;
    int tid = threadIdx.x;
    int s = 0;
    for (int j = 0; j < C; j++) {
        int idx = tid * C + j;
        if (idx < NN_P) s += g_deg[idx];
    }
    sp[tid] = s;
    __syncthreads();
    for (int o = 1; o < 1024; o <<= 1) {
        int t = (tid >= o) ? sp[tid - o] : 0;
        __syncthreads();
        sp[tid] += t;
        __syncthreads();
    }
    int run = sp[tid] - s;
    for (int j = 0; j < C; j++) {
        int idx = tid * C + j;
        if (idx < NN_P) { g_rows[idx] = run; run += g_deg[idx]; }
    }
    if (tid == 1023) g_rows[NN_P] = sp[1023];
}
__global__ void k_escatter(const int* __restrict__ src, const int* __restrict__ dst,
                           const int* __restrict__ et) {
    int i = blockIdx.x * blockDim.x + threadIdx.x;
    if (i < EE) {
        int d = g_pos[dst[i]];
        int pos = g_rows[d] + atomicAdd(&g_cur[d], 1);
        g_epack[pos] = g_pos[src[i]] | (et[i] << 16);
    }
}

// ---------------- adapt: x(gathered) @ W[t] + b, GELU  (K=256) --------------
__global__ void __launch_bounds__(256) k_adapt(const float* __restrict__ x,
                                               const float* __restrict__ W,
                                               const float* __restrict__ b) {
    __shared__ __align__(16) u64 sHT[32 * 128];     // 32 KB, dup'd transposed A
    __shared__ __align__(16) float sW[32 * 128];    // 16 KB
    int tile = blockIdx.x;
    int t = g_tiletype128[tile];
    if (t < 0) return;
    int tid = threadIdx.x;
    int cg = tid & 15, rg = tid >> 4;
    int sr = tid & 127, shf = tid >> 7;           // staging row / half
    int orig = g_ord[tile * 128 + sr];
    const float* Wt = W + (size_t)t * IN_DIM * HID;
    u64 acc[8][4];
#pragma unroll
    for (int i = 0; i < 8; i++)
#pragma unroll
        for (int j = 0; j < 4; j++) acc[i][j] = 0ull;

    for (int kc = 0; kc < 8; kc++) {
        __syncthreads();
        for (int u = tid * 4; u < 32 * HID; u += 1024)
            *(float4*)&sW[u] = *(const float4*)&Wt[kc * 32 * HID + u];
        {
            const float* xr = x + (size_t)orig * IN_DIM + kc * 32 + shf * 16;
#pragma unroll
            for (int q = 0; q < 4; q++) {
                float4 hv = (orig >= 0) ? *(const float4*)&xr[q * 4]
                                        : make_float4(0.f, 0.f, 0.f, 0.f);
                int kb = shf * 16 + q * 4;
                sHT[(kb + 0) * 128 + sr] = dup2(hv.x);
                sHT[(kb + 1) * 128 + sr] = dup2(hv.y);
                sHT[(kb + 2) * 128 + sr] = dup2(hv.z);
                sHT[(kb + 3) * 128 + sr] = dup2(hv.w);
            }
        }
        __syncthreads();
#pragma unroll 4
        for (int k = 0; k < 32; k++) {
            u64 wp[4];
#pragma unroll
            for (int j = 0; j < 4; j++)
                wp[j] = *(const u64*)&sW[k * 128 + cg * 8 + 2 * j];
#pragma unroll
            for (int i = 0; i < 8; i++) {
                u64 hd = sHT[k * 128 + rg * 8 + i];
#pragma unroll
                for (int j = 0; j < 4; j++) ffma2(acc[i][j], hd, wp[j]);
            }
        }
    }
    const float* bt = b + t * HID + cg * 8;
#pragma unroll
    for (int i = 0; i < 8; i++) {
        float* o = &g_h[(size_t)(tile * 128 + rg * 8 + i) * HID + cg * 8];
#pragma unroll
        for (int j = 0; j < 4; j++) {
            float lo, hi;
            unpack2(acc[i][j], lo, hi);
            lo += bt[2 * j]; hi += bt[2 * j + 1];
            lo = 0.5f * lo * (1.f + erff(lo * 0.7071067811865475f));
            hi = 0.5f * hi * (1.f + erff(hi * 0.7071067811865475f));
            *(float2*)&o[2 * j] = make_float2(lo, hi);
        }
    }
}

// ---------------- kqv: h @ {Wk,Wq,Wv}[t]  (K=128, grid.y selects) -----------
__global__ void __launch_bounds__(256) k_kqv(const float* __restrict__ Wk,
                                             const float* __restrict__ Wq,
                                             const float* __restrict__ Wv) {
    __shared__ __align__(16) u64 sHT[32 * 128];
    __shared__ __align__(16) float sW[32 * 128];
    int tile = blockIdx.x;
    int t = g_tiletype128[tile];
    if (t < 0) return;
    int m = blockIdx.y;
    const float* Wt = ((m == 0) ? Wk : (m == 1) ? Wq : Wv) + (size_t)t * HID * HID;
    float* dst = (m == 0) ? g_k : (m == 1) ? g_q : g_v;
    int tid = threadIdx.x;
    int cg = tid & 15, rg = tid >> 4;
    int sr = tid & 127, shf = tid >> 7;
    u64 acc[8][4];
#pragma unroll
    for (int i = 0; i < 8; i++)
#pragma unroll
        for (int j = 0; j < 4; j++) acc[i][j] = 0ull;

    for (int kc = 0; kc < 4; kc++) {
        __syncthreads();
        for (int u = tid * 4; u < 32 * HID; u += 1024)
            *(float4*)&sW[u] = *(const float4*)&Wt[kc * 32 * HID + u];
        {
            const float* hr = &g_h[(size_t)(tile * 128 + sr) * HID + kc * 32 + shf * 16];
#pragma unroll
            for (int q = 0; q < 4; q++) {
                float4 hv = *(const float4*)&hr[q * 4];
                int kb = shf * 16 + q * 4;
                sHT[(kb + 0) * 128 + sr] = dup2(hv.x);
                sHT[(kb + 1) * 128 + sr] = dup2(hv.y);
                sHT[(kb + 2) * 128 + sr] = dup2(hv.z);
                sHT[(kb + 3) * 128 + sr] = dup2(hv.w);
            }
        }
        __syncthreads();
#pragma unroll 4
        for (int k = 0; k < 32; k++) {
            u64 wp[4];
#pragma unroll
            for (int j = 0; j < 4; j++)
                wp[j] = *(const u64*)&sW[k * 128 + cg * 8 + 2 * j];
#pragma unroll
            for (int i = 0; i < 8; i++) {
                u64 hd = sHT[k * 128 + rg * 8 + i];
#pragma unroll
                for (int j = 0; j < 4; j++) ffma2(acc[i][j], hd, wp[j]);
            }
        }
    }
#pragma unroll
    for (int i = 0; i < 8; i++) {
        float* o = &dst[(size_t)(tile * 128 + rg * 8 + i) * HID + cg * 8];
#pragma unroll
        for (int j = 0; j < 4; j++) {
            float lo, hi;
            unpack2(acc[i][j], lo, hi);
            *(float2*)&o[2 * j] = make_float2(lo, hi);
        }
    }
}

// ---------------- post: agg @ Wla[t] -> g_k scratch  (K=128) ----------------
__global__ void __launch_bounds__(256) k_post(const float* __restrict__ Wla) {
    __shared__ __align__(16) u64 sHT[32 * 128];
    __shared__ __align__(16) float sW[32 * 128];
    int tile = blockIdx.x;
    int t = g_tiletype128[tile];
    if (t < 0) return;
    const float* Wt = Wla + (size_t)t * HID * HID;
    int tid = threadIdx.x;
    int cg = tid & 15, rg = tid >> 4;
    int sr = tid & 127, shf = tid >> 7;
    u64 acc[8][4];
#pragma unroll
    for (int i = 0; i < 8; i++)
#pragma unroll
        for (int j = 0; j < 4; j++) acc[i][j] = 0ull;

    for (int kc = 0; kc < 4; kc++) {
        __syncthreads();
        for (int u = tid * 4; u < 32 * HID; u += 1024)
            *(float4*)&sW[u] = *(const float4*)&Wt[kc * 32 * HID + u];
        {
            const float* hr = &g_agg[(size_t)(tile * 128 + sr) * HID + kc * 32 + shf * 16];
#pragma unroll
            for (int q = 0; q < 4; q++) {
                float4 hv = *(const float4*)&hr[q * 4];
                int kb = shf * 16 + q * 4;
                sHT[(kb + 0) * 128 + sr] = dup2(hv.x);
                sHT[(kb + 1) * 128 + sr] = dup2(hv.y);
                sHT[(kb + 2) * 128 + sr] = dup2(hv.z);
                sHT[(kb + 3) * 128 + sr] = dup2(hv.w);
            }
        }
        __syncthreads();
#pragma unroll 4
        for (int k = 0; k < 32; k++) {
            u64 wp[4];
#pragma unroll
            for (int j = 0; j < 4; j++)
                wp[j] = *(const u64*)&sW[k * 128 + cg * 8 + 2 * j];
#pragma unroll
            for (int i = 0; i < 8; i++) {
                u64 hd = sHT[k * 128 + rg * 8 + i];
#pragma unroll
                for (int j = 0; j < 4; j++) ffma2(acc[i][j], hd, wp[j]);
            }
        }
    }
#pragma unroll
    for (int i = 0; i < 8; i++) {
        float* o = &g_k[(size_t)(tile * 128 + rg * 8 + i) * HID + cg * 8];
#pragma unroll
        for (int j = 0; j < 4; j++) {
            float lo, hi;
            unpack2(acc[i][j], lo, hi);
            *(float2*)&o[2 * j] = make_float2(lo, hi);
        }
    }
}

// ---------------- khv: {k,v}[:,h,:] @ {Wa',Wm}[h]  (64x192 tile, K=32) -------
__global__ void __launch_bounds__(192) k_khv(const float* __restrict__ Wa_l,
                                             const float* __restrict__ Wm_l,
                                             const float* __restrict__ pri_l) {
    __shared__ __align__(16) u64 sHT[32 * 64];      // 16 KB
    __shared__ __align__(16) float sW[32 * 192];    // 24 KB
    int tile = blockIdx.x;
    if (g_tiletype128[tile >> 1] < 0) return;
    int h = blockIdx.y, side = blockIdx.z;
    int tid = threadIdx.x;
    int cg = tid % 24, rg = tid / 24;
    const float* Wsrc = side ? Wm_l : Wa_l;
    const float* A = side ? g_v : g_k;
    float* dstp = side ? g_vhat : g_khat;

    for (int u = tid; u < 32 * 192; u += 192) {
        int k = u / 192, c = u % 192, tt = c >> 5, d = c & 31;
        float w = Wsrc[h * TE * 1024 + tt * 1024 + k * 32 + d];
        if (side == 0) w *= pri_l[h * TE + tt] * INV_SQRT_D;
        sW[u] = w;
    }
    int row0 = tile * 64;
    for (int u = tid; u < 64 * 32; u += 192) {
        int r = u >> 5, k = u & 31;
        sHT[k * 64 + r] = dup2(A[(size_t)(row0 + r) * HID + h * DH + k]);
    }
    __syncthreads();

    u64 acc[8][4];
#pragma unroll
    for (int i = 0; i < 8; i++)
#pragma unroll
        for (int j = 0; j < 4; j++) acc[i][j] = 0ull;
#pragma unroll 4
    for (int k = 0; k < 32; k++) {
        u64 wp[4];
#pragma unroll
        for (int j = 0; j < 4; j++)
            wp[j] = *(const u64*)&sW[k * 192 + cg * 8 + 2 * j];
#pragma unroll
        for (int i = 0; i < 8; i++) {
            u64 hd = sHT[k * 64 + rg * 8 + i];
#pragma unroll
            for (int j = 0; j < 4; j++) ffma2(acc[i][j], hd, wp[j]);
        }
    }
    int tt = cg >> 2, d0 = (cg & 3) * 8;
#pragma unroll
    for (int i = 0; i < 8; i++) {
        int row = row0 + rg * 8 + i;
        float* o = &dstp[((size_t)row * TE + tt) * (NHEAD * DH) + h * DH + d0];
#pragma unroll
        for (int j = 0; j < 4; j++) {
            float lo, hi;
            unpack2(acc[i][j], lo, hi);
            *(float2*)&o[2 * j] = make_float2(lo, hi);
        }
    }
}

// ---------------- fused edge softmax + aggregation (CSR, prefetch) ----------
__global__ void k_edge() {
    int wid = threadIdx.x >> 5, lane = threadIdx.x & 31;
    int gw = blockIdx.x * 8 + wid;
    int dstn = gw >> 2, h = gw & 3;
    if (dstn >= NN_P) return;
    int rs = g_rows[dstn], re = g_rows[dstn + 1];
    if (rs == re) { g_agg[dstn * HID + h * DH + lane] = 0.f; return; }
    float qv = g_q[dstn * HID + h * DH + lane];
    float M = -INFINITY, S = 0.f, acc = 0.f;
    int pk = g_epack[rs];
    size_t base = (size_t)(pk & 0xffff) * (TE * NHEAD * DH) + (pk >> 16) * (NHEAD * DH) + h * DH;
    float kh = g_khat[base + lane];
    float vh = g_vhat[base + lane];
    for (int p = rs; p < re; p++) {
        float khc = kh, vhc = vh;
        if (p + 1 < re) {
            int pk2 = g_epack[p + 1];
            size_t b2 = (size_t)(pk2 & 0xffff) * (TE * NHEAD * DH) + (pk2 >> 16) * (NHEAD * DH) + h * DH;
            kh = g_khat[b2 + lane];
            vh = g_vhat[b2 + lane];
        }
        float ph = khc * qv;
#pragma unroll
        for (int o = 16; o > 0; o >>= 1)
            ph += __shfl_xor_sync(0xffffffffu, ph, o);
        float nm = fmaxf(M, ph);
        float scale = __expf(M - nm);
        float w = __expf(ph - nm);
        S = S * scale + w;
        acc = acc * scale + w * vhc;
        M = nm;
    }
    g_agg[dstn * HID + h * DH + lane] = (S > 0.f) ? acc / S : 0.f;
}

// ---------------- skip blend + layernorm (warp per row) ---------------------
__global__ void k_ln(const float* __restrict__ skipv, const float* __restrict__ gam,
                     const float* __restrict__ bet) {
    int wid = threadIdx.x >> 5, lane = threadIdx.x & 31;
    int row = blockIdx.x * 8 + wid;
    if (row >= NN_P) return;
    int t = g_tiletype128[row >> 7];
    if (t < 0) return;
    float alpha = 1.f / (1.f + expf(-skipv[t]));
    float v[4], s1 = 0.f, s2 = 0.f;
#pragma unroll
    for (int r = 0; r < 4; r++) {
        float ha = g_k[(size_t)row * HID + r * 32 + lane];   // g_k = post scratch
        float ho = g_h[(size_t)row * HID + r * 32 + lane];
        v[r] = ha * alpha + ho * (1.f - alpha);
        s1 += v[r]; s2 += v[r] * v[r];
    }
#pragma unroll
    for (int o = 16; o > 0; o >>= 1) {
        s1 += __shfl_xor_sync(0xffffffffu, s1, o);
        s2 += __shfl_xor_sync(0xffffffffu, s2, o);
    }
    float mu = s1 * (1.f / 128.f);
    float var = s2 * (1.f / 128.f) - mu * mu;
    float rstd = rsqrtf(var + 1e-5f);
#pragma unroll
    for (int r = 0; r < 4; r++) {
        int j = r * 32 + lane;
        g_h[(size_t)row * HID + j] = (v[r] - mu) * rstd * gam[j] + bet[j];
    }
}

// ---------------- output projection (orig order) -----------------------------
__global__ void k_out(const float* __restrict__ Wo, const float* __restrict__ bo,
                      float* __restrict__ out) {
    __shared__ float sW[HID * 16];
    int tid = threadIdx.x;
    for (int u = tid; u < HID * 16; u += blockDim.x) sW[u] = Wo[u];
    __syncthreads();
    int gt = blockIdx.x * blockDim.x + tid;
    int stride = gridDim.x * blockDim.x;
    for (int i = gt; i < NN * 16; i += stride) {
        int nidx = i >> 4, j = i & 15;
        int pos = g_pos[nidx];
        const float4* hr = reinterpret_cast<const float4*>(&g_h[(size_t)pos * HID]);
        float acc = bo[j];
#pragma unroll
        for (int kq = 0; kq < HID / 4; kq++) {
            float4 hv = hr[kq];
            acc += hv.x * sW[(4 * kq + 0) * 16 + j];
            acc += hv.y * sW[(4 * kq + 1) * 16 + j];
            acc += hv.z * sW[(4 * kq + 2) * 16 + j];
            acc += hv.w * sW[(4 * kq + 3) * 16 + j];
        }
        out[i] = acc;
    }
}

// ---------------- launch ------------------------------------------------------
extern "C" void kernel_launch(void* const* d_in, const int* in_sizes, int n_in,
                              void* d_out, int out_size) {
    const float* x       = (const float*)d_in[0];
    const float* adapt_W = (const float*)d_in[1];
    const float* adapt_b = (const float*)d_in[2];
    const float* Wk      = (const float*)d_in[3];
    const float* Wq      = (const float*)d_in[4];
    const float* Wv      = (const float*)d_in[5];
    const float* pri     = (const float*)d_in[6];
    const float* Wa      = (const float*)d_in[7];
    const float* Wm      = (const float*)d_in[8];
    const float* Wla     = (const float*)d_in[9];
    const float* skip    = (const float*)d_in[10];
    const float* gamma   = (const float*)d_in[11];
    const float* beta    = (const float*)d_in[12];
    const float* out_W   = (const float*)d_in[13];
    const float* out_b   = (const float*)d_in[14];
    const int*   ntype   = (const int*)d_in[15];
    const int*   etype   = (const int*)d_in[16];
    const int*   src     = (const int*)d_in[17];
    const int*   dst     = (const int*)d_in[18];
    float* out = (float*)d_out;

    k_init<<<(NN_P + 255) / 256, 256>>>();
    k_hist<<<(NN + 255) / 256, 256>>>(ntype);
    k_scan1<<<1, 1>>>();
    k_nscatter<<<(NN + 255) / 256, 256>>>(ntype);

    k_adapt<<<NT128, 256>>>(x, adapt_W, adapt_b);

    bool csr_built = false;
    for (int l = 0; l < 2; l++) {
        dim3 qg(NT128, 3);
        k_kqv<<<qg, 256>>>(Wk + (size_t)l * TN * HID * HID,
                           Wq + (size_t)l * TN * HID * HID,
                           Wv + (size_t)l * TN * HID * HID);
        dim3 hg(NT64, NHEAD, 2);
        k_khv<<<hg, 192>>>(Wa + (size_t)l * NHEAD * TE * DH * DH,
                           Wm + (size_t)l * NHEAD * TE * DH * DH,
                           pri + (size_t)l * NHEAD * TE);
        if (!csr_built) {   // overlap CSR build behind first layer's GEMMs
            k_edeg<<<(EE + 255) / 256, 256>>>(dst);
            k_escan<<<1, 1024>>>();
            k_escatter<<<(EE + 255) / 256, 256>>>(src, dst, etype);
            csr_built = true;
        }
        k_edge<<<NN_P * NHEAD / 8, 256>>>();
        k_post<<<NT128, 256>>>(Wla + (size_t)l * TN * HID * HID);
        k_ln<<<NN_P / 8, 256>>>(skip + (size_t)l * TN,
                                gamma + (size_t)l * HID,
                                beta + (size_t)l * HID);
    }
    k_out<<<400, 256>>>(out_W, out_b, out);
}